// round 1
// baseline (speedup 1.0000x reference)
#include <cuda_runtime.h>
#include <math.h>

#define NB 16
#define CI 512
#define CO 512
#define HW 32
#define SD 512

// Scratch (static __device__ globals — allowed by harness rules)
__device__ float g_s[NB * CI];                 // modulation scales s[b,i]
__device__ float g_alpha[NB * CO];             // wscale * demod[b,o]
__device__ float g_W2[CO * CI];                // sum_k cw^2
__device__ float g_xmod[NB * CI * HW * HW];    // x * s
__device__ float g_Kall[4ull * 9 * CI * CO];   // [phase][tap][i][o]

// 1D composition matrices of (upsample-2 transposed k3) ∘ (blur [1,3,3,1]/4)
// M[r][d][ky]: output parity r, input offset d-1, weight tap ky
__constant__ float c_M[2][3][3] = {
    {{0.00f, 0.25f, 0.75f}, {0.75f, 0.75f, 0.25f}, {0.25f, 0.00f, 0.00f}},
    {{0.00f, 0.00f, 0.25f}, {0.25f, 0.75f, 0.75f}, {0.75f, 0.25f, 0.00f}}
};

// ---------------------------------------------------------------------------
// s[b,i] = style[b,:] @ mod_weight[i,:] / sqrt(512) + mod_bias[i]
__global__ void k_style(const float* __restrict__ style,
                        const float* __restrict__ mw,
                        const float* __restrict__ mb) {
    int b = blockIdx.x, i = threadIdx.x;
    __shared__ float st[SD];
    st[i] = style[b * SD + i];
    __syncthreads();
    const float* row = mw + (size_t)i * SD;
    float acc = 0.f;
#pragma unroll 4
    for (int j = 0; j < SD; j += 4) {
        float4 m = *(const float4*)(row + j);
        acc += m.x * st[j] + m.y * st[j + 1] + m.z * st[j + 2] + m.w * st[j + 3];
    }
    g_s[b * CI + i] = acc * 0.04419417382415922f + mb[i];
}

// W2[o,i] = sum over 9 taps of conv_weight^2
__global__ void k_w2(const float* __restrict__ cw) {
    int tid = blockIdx.x * blockDim.x + threadIdx.x;  // o*512 + i
    if (tid >= CO * CI) return;
    const float* p = cw + (size_t)tid * 9;
    float a = 0.f;
#pragma unroll
    for (int k = 0; k < 9; ++k) a += p[k] * p[k];
    g_W2[tid] = a;
}

// alpha[b,o] = wscale * rsqrt(wscale^2 * sum_i s[b,i]^2 * W2[o,i] + eps)
__global__ void k_alpha() {
    int b = blockIdx.x, o = threadIdx.x;
    __shared__ float s2[CI];
    float sv = g_s[b * CI + o];   // threadIdx doubles as i for the staging load
    s2[o] = sv * sv;
    __syncthreads();
    const float* row = g_W2 + (size_t)o * CI;
    float acc = 0.f;
#pragma unroll 4
    for (int j = 0; j < CI; j += 4) {
        float4 m = *(const float4*)(row + j);
        acc += m.x * s2[j] + m.y * s2[j + 1] + m.z * s2[j + 2] + m.w * s2[j + 3];
    }
    const float wscale2 = 1.0f / 4608.0f;   // (1/sqrt(512*9))^2
    g_alpha[b * CO + o] = 0.014731391274719739f * rsqrtf(wscale2 * acc + 1e-8f);
}

// x_mod = x * s[b,i]
__global__ void k_xmod(const float* __restrict__ x) {
    int idx = blockIdx.x * blockDim.x + threadIdx.x;
    if (idx >= NB * CI * HW * HW) return;
    int bi = idx >> 10;   // (b*512 + i)
    g_xmod[idx] = x[idx] * g_s[bi];
}

// Effective per-phase 3x3 kernels: Kall[phase][tap][i][o]
__global__ void k_weights(const float* __restrict__ cw) {
    int tid = blockIdx.x * blockDim.x + threadIdx.x;  // i*512 + o (o fastest)
    if (tid >= CO * CI) return;
    int o = tid & (CO - 1);
    int i = tid >> 9;
    float w9[9];
#pragma unroll
    for (int k = 0; k < 9; ++k) w9[k] = __ldg(&cw[((size_t)o * CI + i) * 9 + k]);
#pragma unroll
    for (int ry = 0; ry < 2; ++ry) {
        float tmp[3][3];
#pragma unroll
        for (int d = 0; d < 3; ++d)
#pragma unroll
            for (int kx = 0; kx < 3; ++kx)
                tmp[d][kx] = c_M[ry][d][0] * w9[kx] + c_M[ry][d][1] * w9[3 + kx] +
                             c_M[ry][d][2] * w9[6 + kx];
#pragma unroll
        for (int rx = 0; rx < 2; ++rx) {
            int phase = ry * 2 + rx;
#pragma unroll
            for (int d = 0; d < 3; ++d)
#pragma unroll
                for (int dx = 0; dx < 3; ++dx) {
                    float v = c_M[rx][dx][0] * tmp[d][0] + c_M[rx][dx][1] * tmp[d][1] +
                              c_M[rx][dx][2] * tmp[d][2];
                    g_Kall[(((size_t)phase * 9 + d * 3 + dx) * CI + i) * CO + o] = v;
                }
        }
    }
}

// ---------------------------------------------------------------------------
// Main fused conv: per (b, phase, 64 o-chans, 4 rows x 32 cols) block.
// out[b,o,2p+ry,2q+rx] = alpha[b,o] * sum_{i,dy,dx} Kall[ph][..][i][o] * xmod[b,i,p+dy,q+dx]
//                        + nw*noise + bias, leaky(0.2) * sqrt(2)
__global__ void __launch_bounds__(256, 2)
k_conv(const float* __restrict__ noise, const float* __restrict__ nwp,
       const float* __restrict__ act_bias, float* __restrict__ out) {
    int bx = blockIdx.x;               // 0..63: low 3 bits o-tile, high 3 bits row-tile
    int phase = blockIdx.y;            // 0..3
    int b = blockIdx.z;                // 0..15
    int o0 = (bx & 7) * 64;
    int p0 = (bx >> 3) * 4;
    int ry = phase >> 1, rx = phase & 1;

    __shared__ float xs[6 * 36];                     // 6 rows x 34 cols (stride 36)
    __shared__ __align__(16) float As[9 * 64];       // 9 taps x 64 out-ch

    int tid = threadIdx.x;
    int to = tid >> 5;       // warp id 0..7 -> o sub-block
    int ts = tid & 31;       // column q

    unsigned long long acc[4][4];                    // [o-pair e][row r], packed f32x2
#pragma unroll
    for (int e = 0; e < 4; ++e)
#pragma unroll
        for (int r = 0; r < 4; ++r) acc[e][r] = 0ull;

    const float* xmb = g_xmod + (size_t)b * CI * 1024;
    const float* Kp = g_Kall + (size_t)phase * 9 * CI * CO;

    // precompute xs load coords
    int lr = tid / 34, lc = tid % 34;                // valid for tid < 204
    int gy = p0 - 1 + lr, gx = lc - 1;
    bool xok = (tid < 204) && ((unsigned)gy < 32u) && ((unsigned)gx < 32u);

    for (int i = 0; i < CI; ++i) {
        if (tid < 204) xs[lr * 36 + lc] = xok ? xmb[i * 1024 + gy * 32 + gx] : 0.f;
#pragma unroll
        for (int idx = tid; idx < 576; idx += 256) {
            int tap = idx >> 6, oc = idx & 63;
            As[tap * 64 + oc] = Kp[((size_t)tap * CI + i) * CO + o0 + oc];
        }
        __syncthreads();

        const unsigned long long* As64 = (const unsigned long long*)As;
#pragma unroll
        for (int dx = 0; dx < 3; ++dx) {
            unsigned long long xp[6];
#pragma unroll
            for (int r = 0; r < 6; ++r) {
                unsigned xu = __float_as_uint(xs[r * 36 + ts + dx]);
                asm("mov.b64 %0, {%1, %1};" : "=l"(xp[r]) : "r"(xu));
            }
#pragma unroll
            for (int dy = 0; dy < 3; ++dy) {
                int tap = dy * 3 + dx;
#pragma unroll
                for (int e = 0; e < 4; ++e) {
                    unsigned long long av = As64[tap * 32 + to * 4 + e];
#pragma unroll
                    for (int r = 0; r < 4; ++r)
                        asm("fma.rn.f32x2 %0, %1, %2, %0;"
                            : "+l"(acc[e][r]) : "l"(av), "l"(xp[dy + r]));
                }
            }
        }
        __syncthreads();
    }

    // Epilogue
    float nw = *nwp;
    int X = 2 * ts + rx;
    float nz[4];
#pragma unroll
    for (int r = 0; r < 4; ++r) {
        int Y = 2 * (p0 + r) + ry;
        nz[r] = nw * noise[b * 4096 + Y * 64 + X];
    }
#pragma unroll
    for (int e = 0; e < 4; ++e) {
#pragma unroll
        for (int r = 0; r < 4; ++r) {
            unsigned lo, hi;
            asm("mov.b64 {%0, %1}, %2;" : "=r"(lo), "=r"(hi) : "l"(acc[e][r]));
            int Y = 2 * (p0 + r) + ry;
#pragma unroll
            for (int h = 0; h < 2; ++h) {
                int o = o0 + to * 8 + 2 * e + h;
                float v = __uint_as_float(h ? hi : lo);
                v = v * g_alpha[b * CO + o] + nz[r] + act_bias[o];
                v = (v > 0.f ? v : 0.2f * v) * 1.4142135623730951f;
                out[(((size_t)b * CO + o) * 64 + Y) * 64 + X] = v;
            }
        }
    }
}

// ---------------------------------------------------------------------------
extern "C" void kernel_launch(void* const* d_in, const int* in_sizes, int n_in,
                              void* d_out, int out_size) {
    const float* x           = (const float*)d_in[0];
    const float* style       = (const float*)d_in[1];
    const float* noise       = (const float*)d_in[2];
    const float* conv_weight = (const float*)d_in[3];
    const float* mod_weight  = (const float*)d_in[4];
    const float* mod_bias    = (const float*)d_in[5];
    const float* noise_w     = (const float*)d_in[6];
    const float* act_bias    = (const float*)d_in[7];
    float* out = (float*)d_out;

    k_style<<<NB, 512>>>(style, mod_weight, mod_bias);
    k_w2<<<CO, 512>>>(conv_weight);
    k_alpha<<<NB, 512>>>();
    k_xmod<<<(NB * CI * HW * HW + 511) / 512, 512>>>(x);
    k_weights<<<CI, 512>>>(conv_weight);
    k_conv<<<dim3(64, 4, NB), 256>>>(noise, noise_w, act_bias, out);
}

// round 3
// speedup vs baseline: 1.9806x; 1.9806x over previous
#include <cuda_runtime.h>
#include <cuda_bf16.h>
#include <cstdint>
#include <math.h>

#define NB 16
#define CI 512
#define CO 512
#define SD 512

// ---------------------------------------------------------------------------
// Scratch (__device__ globals — allowed)
__device__ float g_s[NB * CI];
__device__ float g_W2[CO * CI];
__device__ float g_alpha[NB * CO];
__device__ __nv_bfloat16 g_xh[(size_t)NB * 34 * 34 * CI];   // padded, i-contig, hi
__device__ __nv_bfloat16 g_xl[(size_t)NB * 34 * 34 * CI];   // lo
__device__ __nv_bfloat16 g_kh[(size_t)4 * 9 * CO * CI];     // [ph][tap][o][i] hi
__device__ __nv_bfloat16 g_kl[(size_t)4 * 9 * CO * CI];     // lo

// (upsample-2 transposed k3) ∘ (blur [1,3,3,1]/4) composition, per parity
__constant__ float c_M[2][3][3] = {
    {{0.00f, 0.25f, 0.75f}, {0.75f, 0.75f, 0.25f}, {0.25f, 0.00f, 0.00f}},
    {{0.00f, 0.00f, 0.25f}, {0.25f, 0.75f, 0.75f}, {0.75f, 0.25f, 0.00f}}
};

// ---------------------------------------------------------------------------
__device__ __forceinline__ uint32_t smem_u32(const void* p) {
    uint32_t a;
    asm("{ .reg .u64 t; cvta.to.shared.u64 t, %1; cvt.u32.u64 %0, t; }"
        : "=r"(a) : "l"(p));
    return a;
}
__device__ __forceinline__ uint32_t lds32(uint32_t a) {
    uint32_t v;
    asm volatile("ld.shared.b32 %0, [%1];" : "=r"(v) : "r"(a));
    return v;
}
__device__ __forceinline__ void sts128(uint32_t a, uint4 v) {
    asm volatile("st.shared.v4.b32 [%0], {%1, %2, %3, %4};"
                 :: "r"(a), "r"(v.x), "r"(v.y), "r"(v.z), "r"(v.w) : "memory");
}
__device__ __forceinline__ void mma_bf16(float* d, const uint32_t* a,
                                         uint32_t b0, uint32_t b1) {
    asm volatile(
        "mma.sync.aligned.m16n8k16.row.col.f32.bf16.bf16.f32 "
        "{%0,%1,%2,%3}, {%4,%5,%6,%7}, {%8,%9}, {%0,%1,%2,%3};"
        : "+f"(d[0]), "+f"(d[1]), "+f"(d[2]), "+f"(d[3])
        : "r"(a[0]), "r"(a[1]), "r"(a[2]), "r"(a[3]), "r"(b0), "r"(b1));
}

// ---------------------------------------------------------------------------
// s[b,i] = style @ mod_weight^T / sqrt(512) + mod_bias
__global__ void k_style(const float* __restrict__ style, const float* __restrict__ mw,
                        const float* __restrict__ mb) {
    int b = blockIdx.x, i = threadIdx.x;
    __shared__ float st[SD];
    st[i] = style[b * SD + i];
    __syncthreads();
    const float* row = mw + (size_t)i * SD;
    float acc = 0.f;
#pragma unroll 4
    for (int j = 0; j < SD; j += 4) {
        float4 m = *(const float4*)(row + j);
        acc += m.x * st[j] + m.y * st[j + 1] + m.z * st[j + 2] + m.w * st[j + 3];
    }
    g_s[b * CI + i] = acc * 0.04419417382415922f + mb[i];
}

__global__ void k_w2(const float* __restrict__ cw) {
    int tid = blockIdx.x * blockDim.x + threadIdx.x;
    if (tid >= CO * CI) return;
    const float* p = cw + (size_t)tid * 9;
    float a = 0.f;
#pragma unroll
    for (int k = 0; k < 9; ++k) a += p[k] * p[k];
    g_W2[tid] = a;
}

__global__ void k_alpha() {
    int b = blockIdx.x, o = threadIdx.x;
    __shared__ float s2[CI];
    float sv = g_s[b * CI + o];
    s2[o] = sv * sv;
    __syncthreads();
    const float* row = g_W2 + (size_t)o * CI;
    float acc = 0.f;
#pragma unroll 4
    for (int j = 0; j < CI; j += 4) {
        float4 m = *(const float4*)(row + j);
        acc += m.x * s2[j] + m.y * s2[j + 1] + m.z * s2[j + 2] + m.w * s2[j + 3];
    }
    const float wscale2 = 1.0f / 4608.0f;
    g_alpha[b * CO + o] = 0.014731391274719739f * rsqrtf(wscale2 * acc + 1e-8f);
}

// xpad[b,y,x,i] = (x[b,i,y-1,x-1] * s[b,i]) split hi/lo, zero on 34x34 border
__global__ void k_xsplit(const float* __restrict__ x) {
    int by = blockIdx.x;
    int b = by / 34, y = by % 34;
    int t = threadIdx.x;   // 128 threads
    bool iny = (y >= 1 && y <= 32);
    unsigned short* ph = (unsigned short*)g_xh;
    unsigned short* pl = (unsigned short*)g_xl;
#pragma unroll 1
    for (int c = 0; c < 4; ++c) {
        int i = c * 128 + t;
        unsigned pk[32];
        if (iny) {
            const float* src = x + ((size_t)(b * CI + i) * 32 + (y - 1)) * 32;
            float sv = g_s[b * CI + i];
#pragma unroll
            for (int q4 = 0; q4 < 8; ++q4) {
                float4 f = *(const float4*)(src + q4 * 4);
                float vv[4] = {f.x, f.y, f.z, f.w};
#pragma unroll
                for (int j = 0; j < 4; ++j) {
                    float v = vv[j] * sv;
                    __nv_bfloat16 hh = __float2bfloat16(v);
                    __nv_bfloat16 ll = __float2bfloat16(v - __bfloat162float(hh));
                    pk[q4 * 4 + j] = (unsigned)__bfloat16_as_ushort(hh) |
                                     ((unsigned)__bfloat16_as_ushort(ll) << 16);
                }
            }
        } else {
#pragma unroll
            for (int j = 0; j < 32; ++j) pk[j] = 0;
        }
        size_t rowbase = (size_t)(b * 34 + y) * 34 * CI + (size_t)i;
#pragma unroll
        for (int xo = 0; xo < 34; ++xo) {
            unsigned pv = (iny && xo >= 1 && xo <= 32) ? pk[xo - 1] : 0u;
            ph[rowbase + (size_t)xo * CI] = (unsigned short)(pv & 0xFFFF);
            pl[rowbase + (size_t)xo * CI] = (unsigned short)(pv >> 16);
        }
    }
}

// Composed per-phase weights -> bf16 hi/lo, layout [ph][tap][o][i]
__global__ void k_wsplit(const float* __restrict__ cw) {
    int tid = blockIdx.x * blockDim.x + threadIdx.x;
    if (tid >= CO * CI) return;
    int o = tid >> 9, i = tid & 511;
    float w9[9];
#pragma unroll
    for (int k = 0; k < 9; ++k) w9[k] = __ldg(&cw[((size_t)o * CI + i) * 9 + k]);
#pragma unroll
    for (int ry = 0; ry < 2; ++ry) {
        float tmp[3][3];
#pragma unroll
        for (int d = 0; d < 3; ++d)
#pragma unroll
            for (int kx = 0; kx < 3; ++kx)
                tmp[d][kx] = c_M[ry][d][0] * w9[kx] + c_M[ry][d][1] * w9[3 + kx] +
                             c_M[ry][d][2] * w9[6 + kx];
#pragma unroll
        for (int rx = 0; rx < 2; ++rx) {
            int phase = ry * 2 + rx;
#pragma unroll
            for (int d = 0; d < 3; ++d)
#pragma unroll
                for (int dx = 0; dx < 3; ++dx) {
                    float v = c_M[rx][dx][0] * tmp[d][0] + c_M[rx][dx][1] * tmp[d][1] +
                              c_M[rx][dx][2] * tmp[d][2];
                    __nv_bfloat16 hh = __float2bfloat16(v);
                    __nv_bfloat16 ll = __float2bfloat16(v - __bfloat162float(hh));
                    size_t off = ((size_t)(phase * 9 + d * 3 + dx) * CO + o) * CI + i;
                    g_kh[off] = hh;
                    g_kl[off] = ll;
                }
        }
    }
}

// ---------------------------------------------------------------------------
// Main GEMM-conv via warp-level mma.sync (bf16 hi/lo 3-pass, fp32 accum).
// CTA: M=128 (o), N=128 (n = 4 p-rows x 32 q), K streamed 144 x 32.
// smem stage (32KB): Ah[8K] Al[8K] Bh[8K] Bl[8K]; rows of 64B, XOR swizzle.
#define NSTG 144

__global__ void __launch_bounds__(256)
k_conv(const float* __restrict__ noise, const float* __restrict__ nwp,
       const float* __restrict__ ab, float* __restrict__ out) {
    extern __shared__ __align__(1024) char smem[];
    const uint32_t sb = smem_u32(smem);

    const int tid = threadIdx.x;
    const int wid = tid >> 5, lane = tid & 31;
    const int b = blockIdx.x >> 3;
    const int pblk = blockIdx.x & 7;
    const int o0 = blockIdx.y * 128;
    const int phase = blockIdx.z;
    const int ry = phase >> 1, rx = phase & 1;
    const int wm = wid & 3, wn = wid >> 2;
    const int g = lane >> 2, t = lane & 3;

    // Fragment LDS base addresses (byte offsets within a tile; XOR-swizzled)
    uint32_t baseA[2][2], baseB[8];
#pragma unroll
    for (int mt = 0; mt < 2; ++mt)
#pragma unroll
        for (int rr = 0; rr < 2; ++rr) {
            int r = wm * 32 + mt * 16 + rr * 8 + g;
            baseA[mt][rr] = (uint32_t)(r * 64 + ((t * 4) ^ ((r & 6) << 3)));
        }
#pragma unroll
    for (int nt = 0; nt < 8; ++nt) {
        int r = wn * 64 + nt * 8 + g;
        baseB[nt] = (uint32_t)(r * 64 + ((t * 4) ^ ((r & 6) << 3)));
    }

    // LDG/STS mapping: thread -> (row r, 32B half h)
    const int r = tid >> 1, h = tid & 1;
    const uint32_t stsc = (uint32_t)(r * 64 + ((h * 32) ^ ((r & 6) << 3)));
    const char* gkh = (const char*)g_kh;
    const char* gkl = (const char*)g_kl;
    const char* gxh = (const char*)g_xh;
    const char* gxl = (const char*)g_xl;

    float acc[2][8][4];
#pragma unroll
    for (int mt = 0; mt < 2; ++mt)
#pragma unroll
        for (int nt = 0; nt < 8; ++nt)
#pragma unroll
            for (int e = 0; e < 4; ++e) acc[mt][nt][e] = 0.f;

    // --- prologue: stage 0 (tap 0 -> dy=dx=0, i0=0) ---
    {
        size_t ao = ((size_t)((phase * 9 + 0) * CO + o0 + r) * CI) * 2 + h * 32;
        size_t bo = ((size_t)((b * 34 + pblk * 4 + (r >> 5)) * 34 + (r & 31)) * CI) * 2 + h * 32;
        uint4 a0 = *(const uint4*)(gkh + ao), a1 = *(const uint4*)(gkh + ao + 16);
        uint4 a2 = *(const uint4*)(gkl + ao), a3 = *(const uint4*)(gkl + ao + 16);
        uint4 b0 = *(const uint4*)(gxh + bo), b1 = *(const uint4*)(gxh + bo + 16);
        uint4 b2 = *(const uint4*)(gxl + bo), b3 = *(const uint4*)(gxl + bo + 16);
        sts128(sb + stsc, a0);          sts128(sb + (stsc ^ 16u), a1);
        sts128(sb + 8192 + stsc, a2);   sts128(sb + 8192 + (stsc ^ 16u), a3);
        sts128(sb + 16384 + stsc, b0);  sts128(sb + 16384 + (stsc ^ 16u), b1);
        sts128(sb + 24576 + stsc, b2);  sts128(sb + 24576 + (stsc ^ 16u), b3);
    }
    __syncthreads();

#pragma unroll 1
    for (int s = 0; s < NSTG; ++s) {
        const uint32_t cb = sb + (uint32_t)((s & 1) << 15);
        uint4 pA0, pA1, pA2, pA3, pB0, pB1, pB2, pB3;
        const bool pf = (s + 1 < NSTG);
        if (pf) {
            int s1 = s + 1;
            int tap1 = s1 >> 4, i01 = (s1 & 15) << 5;
            int dy1 = tap1 / 3, dx1 = tap1 - 3 * dy1;
            size_t ao = (((size_t)(phase * 9 + tap1) * CO + o0 + r) * CI + i01) * 2 + h * 32;
            size_t bo = (((size_t)(b * 34 + pblk * 4 + (r >> 5) + dy1) * 34 +
                          (r & 31) + dx1) * CI + i01) * 2 + h * 32;
            pA0 = *(const uint4*)(gkh + ao); pA1 = *(const uint4*)(gkh + ao + 16);
            pA2 = *(const uint4*)(gkl + ao); pA3 = *(const uint4*)(gkl + ao + 16);
            pB0 = *(const uint4*)(gxh + bo); pB1 = *(const uint4*)(gxh + bo + 16);
            pB2 = *(const uint4*)(gxl + bo); pB3 = *(const uint4*)(gxl + bo + 16);
        }

        // --- MMA over current stage ---
#pragma unroll
        for (int kt = 0; kt < 2; ++kt) {
            const uint32_t kx = (uint32_t)(kt << 5);
            uint32_t ah[2][4], al[2][4];
#pragma unroll
            for (int mt = 0; mt < 2; ++mt) {
                uint32_t c0 = baseA[mt][0] ^ kx, c1 = baseA[mt][1] ^ kx;
                ah[mt][0] = lds32(cb + c0);
                ah[mt][1] = lds32(cb + c1);
                ah[mt][2] = lds32(cb + (c0 ^ 16u));
                ah[mt][3] = lds32(cb + (c1 ^ 16u));
                al[mt][0] = lds32(cb + 8192 + c0);
                al[mt][1] = lds32(cb + 8192 + c1);
                al[mt][2] = lds32(cb + 8192 + (c0 ^ 16u));
                al[mt][3] = lds32(cb + 8192 + (c1 ^ 16u));
            }
#pragma unroll
            for (int nt = 0; nt < 8; ++nt) {
                uint32_t bc = baseB[nt] ^ kx;
                uint32_t bh0 = lds32(cb + 16384 + bc);
                uint32_t bh1 = lds32(cb + 16384 + (bc ^ 16u));
                uint32_t bl0 = lds32(cb + 24576 + bc);
                uint32_t bl1 = lds32(cb + 24576 + (bc ^ 16u));
                mma_bf16(acc[0][nt], ah[0], bh0, bh1);
                mma_bf16(acc[1][nt], ah[1], bh0, bh1);
                mma_bf16(acc[0][nt], ah[0], bl0, bl1);
                mma_bf16(acc[1][nt], ah[1], bl0, bl1);
                mma_bf16(acc[0][nt], al[0], bh0, bh1);
                mma_bf16(acc[1][nt], al[1], bh0, bh1);
            }
        }

        if (pf) {
            const uint32_t nb = sb + (uint32_t)(((s + 1) & 1) << 15);
            sts128(nb + stsc, pA0);          sts128(nb + (stsc ^ 16u), pA1);
            sts128(nb + 8192 + stsc, pA2);   sts128(nb + 8192 + (stsc ^ 16u), pA3);
            sts128(nb + 16384 + stsc, pB0);  sts128(nb + 16384 + (stsc ^ 16u), pB1);
            sts128(nb + 24576 + stsc, pB2);  sts128(nb + 24576 + (stsc ^ 16u), pB3);
        }
        __syncthreads();
    }

    // --- epilogue ---
    const float nw = *nwp;
#pragma unroll
    for (int mt = 0; mt < 2; ++mt)
#pragma unroll
        for (int rr = 0; rr < 2; ++rr) {
            int o = o0 + wm * 32 + mt * 16 + rr * 8 + g;
            float alp = g_alpha[b * CO + o];
            float bia = ab[o];
#pragma unroll
            for (int nt = 0; nt < 8; ++nt)
#pragma unroll
                for (int e = 0; e < 2; ++e) {
                    int nl = wn * 64 + nt * 8 + 2 * t + e;
                    int Y = 2 * (pblk * 4 + (nl >> 5)) + ry;
                    int X = 2 * (nl & 31) + rx;
                    float v = acc[mt][nt][rr * 2 + e] * alp +
                              nw * __ldg(&noise[b * 4096 + Y * 64 + X]) + bia;
                    v = (v > 0.f ? v : 0.2f * v) * 1.4142135623730951f;
                    out[((size_t)(b * CO + o) * 64 + Y) * 64 + X] = v;
                }
        }
}

// ---------------------------------------------------------------------------
extern "C" void kernel_launch(void* const* d_in, const int* in_sizes, int n_in,
                              void* d_out, int out_size) {
    const float* x           = (const float*)d_in[0];
    const float* style       = (const float*)d_in[1];
    const float* noise       = (const float*)d_in[2];
    const float* conv_weight = (const float*)d_in[3];
    const float* mod_weight  = (const float*)d_in[4];
    const float* mod_bias    = (const float*)d_in[5];
    const float* noise_w     = (const float*)d_in[6];
    const float* act_bias    = (const float*)d_in[7];
    float* out = (float*)d_out;

    cudaFuncSetAttribute(k_conv, cudaFuncAttributeMaxDynamicSharedMemorySize, 65536);

    k_style<<<NB, 512>>>(style, mod_weight, mod_bias);
    k_w2<<<512, 512>>>(conv_weight);
    k_alpha<<<NB, 512>>>();
    k_xsplit<<<NB * 34, 128>>>(x);
    k_wsplit<<<1024, 256>>>(conv_weight);
    k_conv<<<dim3(128, 4, 4), 256, 65536>>>(noise, noise_w, act_bias, out);
}

// round 4
// speedup vs baseline: 5.2967x; 2.6742x over previous
#include <cuda_runtime.h>
#include <cuda_bf16.h>
#include <cstdint>
#include <math.h>

#define NB 16
#define CI 512
#define CO 512
#define SD 512

// ---------------------------------------------------------------------------
// Scratch (__device__ globals — allowed)
__device__ float g_s[NB * CI];
__device__ float g_W2[CO * CI];
__device__ float g_alpha[NB * CO];
__device__ __nv_bfloat16 g_xh[(size_t)NB * 34 * 34 * CI];   // padded, i-contig, hi
__device__ __nv_bfloat16 g_xl[(size_t)NB * 34 * 34 * CI];   // lo
__device__ __nv_bfloat16 g_kh[(size_t)9 * CO * CI];         // [tap][o][i] hi
__device__ __nv_bfloat16 g_kl[(size_t)9 * CO * CI];         // lo
__device__ float g_z[(size_t)NB * CO * 9 * 1024];           // [b][o][tap][32x32]

// (upsample-2 transposed k3) ∘ (blur [1,3,3,1]/4) composition, per parity
__constant__ float c_M[2][3][3] = {
    {{0.00f, 0.25f, 0.75f}, {0.75f, 0.75f, 0.25f}, {0.25f, 0.00f, 0.00f}},
    {{0.00f, 0.00f, 0.25f}, {0.25f, 0.75f, 0.75f}, {0.75f, 0.25f, 0.00f}}
};

// ---------------------------------------------------------------------------
__device__ __forceinline__ uint32_t smem_u32(const void* p) {
    uint32_t a;
    asm("{ .reg .u64 t; cvta.to.shared.u64 t, %1; cvt.u32.u64 %0, t; }"
        : "=r"(a) : "l"(p));
    return a;
}
__device__ __forceinline__ uint32_t lds32(uint32_t a) {
    uint32_t v;
    asm volatile("ld.shared.b32 %0, [%1];" : "=r"(v) : "r"(a));
    return v;
}
__device__ __forceinline__ void sts128(uint32_t a, uint4 v) {
    asm volatile("st.shared.v4.b32 [%0], {%1, %2, %3, %4};"
                 :: "r"(a), "r"(v.x), "r"(v.y), "r"(v.z), "r"(v.w) : "memory");
}
__device__ __forceinline__ void mma_bf16(float* d, const uint32_t* a,
                                         uint32_t b0, uint32_t b1) {
    asm volatile(
        "mma.sync.aligned.m16n8k16.row.col.f32.bf16.bf16.f32 "
        "{%0,%1,%2,%3}, {%4,%5,%6,%7}, {%8,%9}, {%0,%1,%2,%3};"
        : "+f"(d[0]), "+f"(d[1]), "+f"(d[2]), "+f"(d[3])
        : "r"(a[0]), "r"(a[1]), "r"(a[2]), "r"(a[3]), "r"(b0), "r"(b1));
}

// ---------------------------------------------------------------------------
__global__ void k_style(const float* __restrict__ style, const float* __restrict__ mw,
                        const float* __restrict__ mb) {
    int b = blockIdx.x, i = threadIdx.x;
    __shared__ float st[SD];
    st[i] = style[b * SD + i];
    __syncthreads();
    const float* row = mw + (size_t)i * SD;
    float acc = 0.f;
#pragma unroll 4
    for (int j = 0; j < SD; j += 4) {
        float4 m = *(const float4*)(row + j);
        acc += m.x * st[j] + m.y * st[j + 1] + m.z * st[j + 2] + m.w * st[j + 3];
    }
    g_s[b * CI + i] = acc * 0.04419417382415922f + mb[i];
}

__global__ void k_w2(const float* __restrict__ cw) {
    int tid = blockIdx.x * blockDim.x + threadIdx.x;
    if (tid >= CO * CI) return;
    const float* p = cw + (size_t)tid * 9;
    float a = 0.f;
#pragma unroll
    for (int k = 0; k < 9; ++k) a += p[k] * p[k];
    g_W2[tid] = a;
}

__global__ void k_alpha() {
    int b = blockIdx.x, o = threadIdx.x;
    __shared__ float s2[CI];
    float sv = g_s[b * CI + o];
    s2[o] = sv * sv;
    __syncthreads();
    const float* row = g_W2 + (size_t)o * CI;
    float acc = 0.f;
#pragma unroll 4
    for (int j = 0; j < CI; j += 4) {
        float4 m = *(const float4*)(row + j);
        acc += m.x * s2[j] + m.y * s2[j + 1] + m.z * s2[j + 2] + m.w * s2[j + 3];
    }
    const float wscale2 = 1.0f / 4608.0f;
    g_alpha[b * CO + o] = 0.014731391274719739f * rsqrtf(wscale2 * acc + 1e-8f);
}

// xpad[b,y,x,i] = (x[b,i,y-1,x-1] * s[b,i]) split hi/lo, zero on 34x34 border
__global__ void k_xsplit(const float* __restrict__ x) {
    int by = blockIdx.x;
    int b = by / 34, y = by % 34;
    int t = threadIdx.x;   // 128 threads
    bool iny = (y >= 1 && y <= 32);
    unsigned short* ph = (unsigned short*)g_xh;
    unsigned short* pl = (unsigned short*)g_xl;
#pragma unroll 1
    for (int c = 0; c < 4; ++c) {
        int i = c * 128 + t;
        unsigned pk[32];
        if (iny) {
            const float* src = x + ((size_t)(b * CI + i) * 32 + (y - 1)) * 32;
            float sv = g_s[b * CI + i];
#pragma unroll
            for (int q4 = 0; q4 < 8; ++q4) {
                float4 f = *(const float4*)(src + q4 * 4);
                float vv[4] = {f.x, f.y, f.z, f.w};
#pragma unroll
                for (int j = 0; j < 4; ++j) {
                    float v = vv[j] * sv;
                    __nv_bfloat16 hh = __float2bfloat16(v);
                    __nv_bfloat16 ll = __float2bfloat16(v - __bfloat162float(hh));
                    pk[q4 * 4 + j] = (unsigned)__bfloat16_as_ushort(hh) |
                                     ((unsigned)__bfloat16_as_ushort(ll) << 16);
                }
            }
        } else {
#pragma unroll
            for (int j = 0; j < 32; ++j) pk[j] = 0;
        }
        size_t rowbase = (size_t)(b * 34 + y) * 34 * CI + (size_t)i;
#pragma unroll
        for (int xo = 0; xo < 34; ++xo) {
            unsigned pv = (iny && xo >= 1 && xo <= 32) ? pk[xo - 1] : 0u;
            ph[rowbase + (size_t)xo * CI] = (unsigned short)(pv & 0xFFFF);
            pl[rowbase + (size_t)xo * CI] = (unsigned short)(pv >> 16);
        }
    }
}

// raw taps -> bf16 hi/lo, layout [tap][o][i]
__global__ void k_wsplit(const float* __restrict__ cw) {
    int tid = blockIdx.x * blockDim.x + threadIdx.x;
    if (tid >= CO * CI) return;
    int o = tid >> 9, i = tid & 511;
#pragma unroll
    for (int k = 0; k < 9; ++k) {
        float v = __ldg(&cw[((size_t)o * CI + i) * 9 + k]);
        __nv_bfloat16 hh = __float2bfloat16(v);
        __nv_bfloat16 ll = __float2bfloat16(v - __bfloat162float(hh));
        size_t off = ((size_t)k * CO + o) * CI + i;
        g_kh[off] = hh;
        g_kl[off] = ll;
    }
}

// ---------------------------------------------------------------------------
// z GEMM: z[b,o,tap,sp] = sum_i w[tap,o,i] * xm[b,i,sp]  (bf16 hi/lo 3-pass)
// CTA: M=128 rows of (tap,o), N=128 (4 p-rows x 32 q), K = 512 in 16 stages.
#define NSTG 16

__global__ void __launch_bounds__(256)
k_zgemm() {
    extern __shared__ __align__(1024) char smem[];
    const uint32_t sb = smem_u32(smem);

    const int tid = threadIdx.x;
    const int wid = tid >> 5, lane = tid & 5 * 6 + 1;  // placeholder fixed below
    const int ln = tid & 31;
    const int b = blockIdx.x >> 3;
    const int pblk = blockIdx.x & 7;
    const int row0 = blockIdx.y * 128;
    const int tp = row0 >> 9;           // tap
    const int o0 = row0 & 511;
    const int wm = wid & 3, wn = wid >> 2;
    const int g = ln >> 2, tq = ln & 3;
    (void)lane;

    uint32_t baseA[2][2], baseB[8];
#pragma unroll
    for (int mt = 0; mt < 2; ++mt)
#pragma unroll
        for (int rr = 0; rr < 2; ++rr) {
            int r = wm * 32 + mt * 16 + rr * 8 + g;
            baseA[mt][rr] = (uint32_t)(r * 64 + ((tq * 4) ^ ((r & 6) << 3)));
        }
#pragma unroll
    for (int nt = 0; nt < 8; ++nt) {
        int r = wn * 64 + nt * 8 + g;
        baseB[nt] = (uint32_t)(r * 64 + ((tq * 4) ^ ((r & 6) << 3)));
    }

    const int r = tid >> 1, h = tid & 1;
    const uint32_t stsc = (uint32_t)(r * 64 + ((h * 32) ^ ((r & 6) << 3)));
    const char* gkh = (const char*)g_kh;
    const char* gkl = (const char*)g_kl;
    const char* gxh = (const char*)g_xh;
    const char* gxl = (const char*)g_xl;

    // A row r -> (tap tp, o0+r); B row r -> interior (pblk*4 + r>>5, r&31)
    const size_t aRow = ((size_t)tp * CO + o0 + r) * CI;
    const size_t bRow = ((size_t)(b * 34 + pblk * 4 + (r >> 5) + 1) * 34 +
                         (r & 31) + 1) * CI;

    float acc[2][8][4];
#pragma unroll
    for (int mt = 0; mt < 2; ++mt)
#pragma unroll
        for (int nt = 0; nt < 8; ++nt)
#pragma unroll
            for (int e = 0; e < 4; ++e) acc[mt][nt][e] = 0.f;

    // prologue: stage 0
    {
        size_t ao = aRow * 2 + h * 32;
        size_t bo = bRow * 2 + h * 32;
        uint4 a0 = *(const uint4*)(gkh + ao), a1 = *(const uint4*)(gkh + ao + 16);
        uint4 a2 = *(const uint4*)(gkl + ao), a3 = *(const uint4*)(gkl + ao + 16);
        uint4 b0 = *(const uint4*)(gxh + bo), b1 = *(const uint4*)(gxh + bo + 16);
        uint4 b2 = *(const uint4*)(gxl + bo), b3 = *(const uint4*)(gxl + bo + 16);
        sts128(sb + stsc, a0);          sts128(sb + (stsc ^ 16u), a1);
        sts128(sb + 8192 + stsc, a2);   sts128(sb + 8192 + (stsc ^ 16u), a3);
        sts128(sb + 16384 + stsc, b0);  sts128(sb + 16384 + (stsc ^ 16u), b1);
        sts128(sb + 24576 + stsc, b2);  sts128(sb + 24576 + (stsc ^ 16u), b3);
    }
    __syncthreads();

#pragma unroll 1
    for (int s = 0; s < NSTG; ++s) {
        const uint32_t cb = sb + (uint32_t)((s & 1) << 15);
        uint4 pA0, pA1, pA2, pA3, pB0, pB1, pB2, pB3;
        const bool pf = (s + 1 < NSTG);
        if (pf) {
            size_t i01 = (size_t)(s + 1) << 5;
            size_t ao = (aRow + i01) * 2 + h * 32;
            size_t bo = (bRow + i01) * 2 + h * 32;
            pA0 = *(const uint4*)(gkh + ao); pA1 = *(const uint4*)(gkh + ao + 16);
            pA2 = *(const uint4*)(gkl + ao); pA3 = *(const uint4*)(gkl + ao + 16);
            pB0 = *(const uint4*)(gxh + bo); pB1 = *(const uint4*)(gxh + bo + 16);
            pB2 = *(const uint4*)(gxl + bo); pB3 = *(const uint4*)(gxl + bo + 16);
        }

#pragma unroll
        for (int kt = 0; kt < 2; ++kt) {
            const uint32_t kx = (uint32_t)(kt << 5);
            uint32_t ah[2][4], al[2][4];
#pragma unroll
            for (int mt = 0; mt < 2; ++mt) {
                uint32_t c0 = baseA[mt][0] ^ kx, c1 = baseA[mt][1] ^ kx;
                ah[mt][0] = lds32(cb + c0);
                ah[mt][1] = lds32(cb + c1);
                ah[mt][2] = lds32(cb + (c0 ^ 16u));
                ah[mt][3] = lds32(cb + (c1 ^ 16u));
                al[mt][0] = lds32(cb + 8192 + c0);
                al[mt][1] = lds32(cb + 8192 + c1);
                al[mt][2] = lds32(cb + 8192 + (c0 ^ 16u));
                al[mt][3] = lds32(cb + 8192 + (c1 ^ 16u));
            }
#pragma unroll
            for (int nt = 0; nt < 8; ++nt) {
                uint32_t bc = baseB[nt] ^ kx;
                uint32_t bh0 = lds32(cb + 16384 + bc);
                uint32_t bh1 = lds32(cb + 16384 + (bc ^ 16u));
                uint32_t bl0 = lds32(cb + 24576 + bc);
                uint32_t bl1 = lds32(cb + 24576 + (bc ^ 16u));
                mma_bf16(acc[0][nt], ah[0], bh0, bh1);
                mma_bf16(acc[1][nt], ah[1], bh0, bh1);
                mma_bf16(acc[0][nt], ah[0], bl0, bl1);
                mma_bf16(acc[1][nt], ah[1], bl0, bl1);
                mma_bf16(acc[0][nt], al[0], bh0, bh1);
                mma_bf16(acc[1][nt], al[1], bh0, bh1);
            }
        }

        if (pf) {
            const uint32_t nb = sb + (uint32_t)(((s + 1) & 1) << 15);
            sts128(nb + stsc, pA0);          sts128(nb + (stsc ^ 16u), pA1);
            sts128(nb + 8192 + stsc, pA2);   sts128(nb + 8192 + (stsc ^ 16u), pA3);
            sts128(nb + 16384 + stsc, pB0);  sts128(nb + 16384 + (stsc ^ 16u), pB1);
            sts128(nb + 24576 + stsc, pB2);  sts128(nb + 24576 + (stsc ^ 16u), pB3);
        }
        __syncthreads();
    }

    // epilogue: write z[b][o][tp][sp]
#pragma unroll
    for (int mt = 0; mt < 2; ++mt)
#pragma unroll
        for (int rr = 0; rr < 2; ++rr) {
            int o = o0 + wm * 32 + mt * 16 + rr * 8 + g;
            float* zb = g_z + ((size_t)(b * CO + o) * 9 + tp) * 1024;
#pragma unroll
            for (int nt = 0; nt < 8; ++nt) {
                int nl = wn * 64 + nt * 8 + 2 * tq;
                int sp = (pblk * 4 + (nl >> 5)) * 32 + (nl & 31);
                float2 v = make_float2(acc[mt][nt][rr * 2], acc[mt][nt][rr * 2 + 1]);
                *(float2*)(zb + sp) = v;
            }
        }
}

// ---------------------------------------------------------------------------
// Combine: per (b,o) apply separable phase stencil + epilogue.
__global__ void __launch_bounds__(256)
k_comb(const float* __restrict__ noise, const float* __restrict__ nwp,
       const float* __restrict__ ab, float* __restrict__ out) {
    extern __shared__ float sm[];
    float* zs = sm;              // 9 * 1024
    float* us = sm + 9216;       // 3 * 32 * 64

    const int bo = blockIdx.x;
    const int b = bo >> 9, o = bo & 511;
    const int tid = threadIdx.x;

    const float* zp = g_z + (size_t)bo * 9216;
#pragma unroll 4
    for (int j = tid; j < 9216; j += 256) zs[j] = zp[j];
    __syncthreads();

    // x-direction: us[ky][y][X] = sum_{dx,kx} M[rx][dx][kx] * zs[ky*3+kx][y][q-1+dx]
#pragma unroll 1
    for (int j = tid; j < 6144; j += 256) {
        int X = j & 63, y = (j >> 6) & 31, ky = j >> 11;
        int rx = X & 1, q = X >> 1;
        float a = 0.f;
#pragma unroll
        for (int dx = 0; dx < 3; ++dx) {
            int qq = q - 1 + dx;
            if (qq >= 0 && qq < 32) {
#pragma unroll
                for (int kx = 0; kx < 3; ++kx)
                    a += c_M[rx][dx][kx] * zs[(ky * 3 + kx) * 1024 + y * 32 + qq];
            }
        }
        us[j] = a;
    }
    __syncthreads();

    const float alp = g_alpha[b * CO + o];
    const float bia = ab[o];
    const float nw = *nwp;
#pragma unroll 1
    for (int j = tid; j < 4096; j += 256) {
        int X = j & 63, Y = j >> 6;
        int ry = Y & 1, p = Y >> 1;
        float a = 0.f;
#pragma unroll
        for (int dy = 0; dy < 3; ++dy) {
            int pp = p - 1 + dy;
            if (pp >= 0 && pp < 32) {
#pragma unroll
                for (int ky = 0; ky < 3; ++ky)
                    a += c_M[ry][dy][ky] * us[ky * 2048 + pp * 64 + X];
            }
        }
        float v = a * alp + nw * __ldg(&noise[b * 4096 + j]) + bia;
        v = (v > 0.f ? v : 0.2f * v) * 1.4142135623730951f;
        out[(size_t)bo * 4096 + j] = v;
    }
}

// ---------------------------------------------------------------------------
extern "C" void kernel_launch(void* const* d_in, const int* in_sizes, int n_in,
                              void* d_out, int out_size) {
    const float* x           = (const float*)d_in[0];
    const float* style       = (const float*)d_in[1];
    const float* noise       = (const float*)d_in[2];
    const float* conv_weight = (const float*)d_in[3];
    const float* mod_weight  = (const float*)d_in[4];
    const float* mod_bias    = (const float*)d_in[5];
    const float* noise_w     = (const float*)d_in[6];
    const float* act_bias    = (const float*)d_in[7];
    float* out = (float*)d_out;

    cudaFuncSetAttribute(k_zgemm, cudaFuncAttributeMaxDynamicSharedMemorySize, 65536);
    cudaFuncSetAttribute(k_comb, cudaFuncAttributeMaxDynamicSharedMemorySize, 61440);

    k_style<<<NB, 512>>>(style, mod_weight, mod_bias);
    k_w2<<<512, 512>>>(conv_weight);
    k_alpha<<<NB, 512>>>();
    k_xsplit<<<NB * 34, 128>>>(x);
    k_wsplit<<<512, 512>>>(conv_weight);
    k_zgemm<<<dim3(128, 36), 256, 65536>>>();
    k_comb<<<NB * CO, 256, 61440>>>(noise, noise_w, act_bias, out);
}

// round 5
// speedup vs baseline: 10.8181x; 2.0424x over previous
#include <cuda_runtime.h>
#include <cuda_fp16.h>
#include <cstdint>
#include <math.h>

#define NB 16
#define CI 512
#define CO 512
#define SD 512

// ---------------------------------------------------------------------------
// Scratch (__device__ globals — allowed)
__device__ float g_s[NB * CI];
__device__ float g_W2[CO * CI];
__device__ float g_alpha[NB * CO];
__device__ __half g_x[(size_t)NB * 32 * 32 * CI];   // [b][y][x][i] fp16, modulated
__device__ __half g_k[(size_t)9 * CO * CI];         // [tap][o][i] fp16
__device__ float g_z[(size_t)NB * CO * 9 * 1024];   // [b][o][tap][32x32]

// (upsample-2 transposed k3) ∘ (blur [1,3,3,1]/4) composition, per parity
__constant__ float c_M[2][3][3] = {
    {{0.00f, 0.25f, 0.75f}, {0.75f, 0.75f, 0.25f}, {0.25f, 0.00f, 0.00f}},
    {{0.00f, 0.00f, 0.25f}, {0.25f, 0.75f, 0.75f}, {0.75f, 0.25f, 0.00f}}
};

// ---------------------------------------------------------------------------
__device__ __forceinline__ uint32_t smem_u32(const void* p) {
    uint32_t a;
    asm("{ .reg .u64 t; cvta.to.shared.u64 t, %1; cvt.u32.u64 %0, t; }"
        : "=r"(a) : "l"(p));
    return a;
}
__device__ __forceinline__ void cp16(uint32_t dst, const void* src) {
    asm volatile("cp.async.cg.shared.global [%0], [%1], 16;"
                 :: "r"(dst), "l"(src) : "memory");
}
__device__ __forceinline__ void cp_commit() {
    asm volatile("cp.async.commit_group;" ::: "memory");
}
__device__ __forceinline__ void ldmx4(uint32_t* r, uint32_t addr) {
    asm volatile("ldmatrix.sync.aligned.m8n8.x4.shared.b16 {%0,%1,%2,%3}, [%4];"
                 : "=r"(r[0]), "=r"(r[1]), "=r"(r[2]), "=r"(r[3]) : "r"(addr));
}
__device__ __forceinline__ void mma_f16(float* d, const uint32_t* a,
                                        uint32_t b0, uint32_t b1) {
    asm volatile(
        "mma.sync.aligned.m16n8k16.row.col.f32.f16.f16.f32 "
        "{%0,%1,%2,%3}, {%4,%5,%6,%7}, {%8,%9}, {%0,%1,%2,%3};"
        : "+f"(d[0]), "+f"(d[1]), "+f"(d[2]), "+f"(d[3])
        : "r"(a[0]), "r"(a[1]), "r"(a[2]), "r"(a[3]), "r"(b0), "r"(b1));
}

// ---------------------------------------------------------------------------
__global__ void k_style(const float* __restrict__ style, const float* __restrict__ mw,
                        const float* __restrict__ mb) {
    int b = blockIdx.x, i = threadIdx.x;
    __shared__ float st[SD];
    st[i] = style[b * SD + i];
    __syncthreads();
    const float* row = mw + (size_t)i * SD;
    float acc = 0.f;
#pragma unroll 4
    for (int j = 0; j < SD; j += 4) {
        float4 m = *(const float4*)(row + j);
        acc += m.x * st[j] + m.y * st[j + 1] + m.z * st[j + 2] + m.w * st[j + 3];
    }
    g_s[b * CI + i] = acc * 0.04419417382415922f + mb[i];
}

__global__ void k_w2(const float* __restrict__ cw) {
    int tid = blockIdx.x * blockDim.x + threadIdx.x;
    if (tid >= CO * CI) return;
    const float* p = cw + (size_t)tid * 9;
    float a = 0.f;
#pragma unroll
    for (int k = 0; k < 9; ++k) a += p[k] * p[k];
    g_W2[tid] = a;
}

__global__ void k_alpha() {
    int b = blockIdx.x, o = threadIdx.x;
    __shared__ float s2[CI];
    float sv = g_s[b * CI + o];
    s2[o] = sv * sv;
    __syncthreads();
    const float* row = g_W2 + (size_t)o * CI;
    float acc = 0.f;
#pragma unroll 4
    for (int j = 0; j < CI; j += 4) {
        float4 m = *(const float4*)(row + j);
        acc += m.x * s2[j] + m.y * s2[j + 1] + m.z * s2[j + 2] + m.w * s2[j + 3];
    }
    const float wscale2 = 1.0f / 4608.0f;
    g_alpha[b * CO + o] = 0.014731391274719739f * rsqrtf(wscale2 * acc + 1e-8f);
}

// g_x[b,y,q,i] = fp16(x[b,i,y,q] * s[b,i])    (transpose to i-contiguous)
__global__ void k_xsplit(const float* __restrict__ x) {
    int by = blockIdx.x;
    int b = by >> 5, y = by & 31;
    int t = threadIdx.x;   // 128 threads
    unsigned short* px = (unsigned short*)g_x;
#pragma unroll 1
    for (int c = 0; c < 4; ++c) {
        int i = c * 128 + t;
        const float* src = x + ((size_t)(b * CI + i) * 32 + y) * 32;
        float sv = g_s[b * CI + i];
        unsigned short pk[32];
#pragma unroll
        for (int q4 = 0; q4 < 8; ++q4) {
            float4 f = *(const float4*)(src + q4 * 4);
            pk[q4 * 4 + 0] = __half_as_ushort(__float2half_rn(f.x * sv));
            pk[q4 * 4 + 1] = __half_as_ushort(__float2half_rn(f.y * sv));
            pk[q4 * 4 + 2] = __half_as_ushort(__float2half_rn(f.z * sv));
            pk[q4 * 4 + 3] = __half_as_ushort(__float2half_rn(f.w * sv));
        }
        size_t rowbase = (size_t)(b * 32 + y) * 32 * CI + (size_t)i;
#pragma unroll
        for (int q = 0; q < 32; ++q)
            px[rowbase + (size_t)q * CI] = pk[q];
    }
}

// raw taps -> fp16, layout [tap][o][i]
__global__ void k_wsplit(const float* __restrict__ cw) {
    int tid = blockIdx.x * blockDim.x + threadIdx.x;
    if (tid >= CO * CI) return;
    int o = tid >> 9, i = tid & 511;
#pragma unroll
    for (int k = 0; k < 9; ++k) {
        float v = __ldg(&cw[((size_t)o * CI + i) * 9 + k]);
        g_k[((size_t)k * CO + o) * CI + i] = __float2half_rn(v);
    }
}

// ---------------------------------------------------------------------------
// z GEMM: z[b,o,tap,sp] = sum_i w[tap,o,i] * xm[b,i,sp]   (fp16, fp32 accum)
// CTA: M=128 rows of (tap,o), N=128 (4 p-rows x 32 q), K=512 in 16 stages.
// 4-stage cp.async pipeline; ldmatrix fragments; 8 warps each 32x64.
#define KSTG 16
#define STG_B 16384

__global__ void __launch_bounds__(256, 2)
k_zgemm() {
    extern __shared__ __align__(1024) char smem[];
    const uint32_t sb = smem_u32(smem);

    const int tid = threadIdx.x;
    const int wid = tid >> 5, ln = tid & 31;
    const int b = blockIdx.x >> 3;
    const int pblk = blockIdx.x & 7;
    const int row0 = blockIdx.y * 128;
    const int tp = row0 >> 9;
    const int o0 = row0 & 511;
    const int wm = wid & 3, wn = wid >> 2;
    const int g = ln >> 2, t4 = ln & 3;

    // --- cp.async chunk assignment: 2 chunks each for A and B per thread ---
    const char* gA = (const char*)g_k;
    const char* gB = (const char*)g_x;
    const char* srcA[2];
    const char* srcB[2];
    uint32_t dstA[2], dstB[2];
#pragma unroll
    for (int j = 0; j < 2; ++j) {
        int id = tid + 256 * j;
        int r = id >> 2;
        uint32_t c = (uint32_t)(id & 3) << 4;
        srcA[j] = gA + ((size_t)(tp * CO + o0 + r) * CI) * 2 + c;
        srcB[j] = gB + ((size_t)((b * 32 + pblk * 4 + (r >> 5)) * 32 + (r & 31)) * CI) * 2 + c;
        uint32_t sw = c ^ (uint32_t)((r & 6) << 3);
        dstA[j] = sb + (uint32_t)(r * 64) + sw;
        dstB[j] = sb + 8192 + (uint32_t)(r * 64) + sw;
    }

    // --- ldmatrix per-lane fragment addresses (stage 0, kt 0) ---
    uint32_t aAddr[2], bAddr[4];
#pragma unroll
    for (int mt = 0; mt < 2; ++mt) {
        int mrow = wm * 32 + mt * 16 + (ln & 15);
        uint32_t hi = (uint32_t)(ln >> 4) << 4;
        aAddr[mt] = sb + (uint32_t)(mrow * 64) + (hi ^ (uint32_t)((mrow & 6) << 3));
    }
#pragma unroll
    for (int np = 0; np < 4; ++np) {
        int nrow = wn * 64 + np * 16 + ((ln >> 4) & 1) * 8 + (ln & 7);
        uint32_t hi = (uint32_t)((ln >> 3) & 1) << 4;
        bAddr[np] = sb + 8192 + (uint32_t)(nrow * 64) + (hi ^ (uint32_t)((nrow & 6) << 3));
    }

    float acc[2][8][4];
#pragma unroll
    for (int mt = 0; mt < 2; ++mt)
#pragma unroll
        for (int nt = 0; nt < 8; ++nt)
#pragma unroll
            for (int e = 0; e < 4; ++e) acc[mt][nt][e] = 0.f;

    // --- prologue: issue stages 0..2 ---
#pragma unroll
    for (int s = 0; s < 3; ++s) {
        uint32_t so = (uint32_t)(s & 3) * STG_B;
        uint32_t go = (uint32_t)s * 64;
#pragma unroll
        for (int j = 0; j < 2; ++j) {
            cp16(dstA[j] + so, srcA[j] + go);
            cp16(dstB[j] + so, srcB[j] + go);
        }
        cp_commit();
    }

#pragma unroll 1
    for (int s = 0; s < KSTG; ++s) {
        asm volatile("cp.async.wait_group 2;" ::: "memory");
        __syncthreads();

        // issue stage s+3 into slot (s+3)&3 (safe: compute s-1 done everywhere)
        if (s + 3 < KSTG) {
            uint32_t so = (uint32_t)((s + 3) & 3) * STG_B;
            uint32_t go = (uint32_t)(s + 3) * 64;
#pragma unroll
            for (int j = 0; j < 2; ++j) {
                cp16(dstA[j] + so, srcA[j] + go);
                cp16(dstB[j] + so, srcB[j] + go);
            }
        }
        cp_commit();

        const uint32_t so = (uint32_t)(s & 3) * STG_B;
#pragma unroll
        for (int kt = 0; kt < 2; ++kt) {
            const uint32_t kx = (uint32_t)(kt << 5);
            uint32_t a[2][4];
            ldmx4(a[0], (aAddr[0] + so) ^ kx);
            ldmx4(a[1], (aAddr[1] + so) ^ kx);
#pragma unroll
            for (int np = 0; np < 4; ++np) {
                uint32_t bb[4];
                ldmx4(bb, (bAddr[np] + so) ^ kx);
                mma_f16(acc[0][2 * np],     a[0], bb[0], bb[1]);
                mma_f16(acc[0][2 * np + 1], a[0], bb[2], bb[3]);
                mma_f16(acc[1][2 * np],     a[1], bb[0], bb[1]);
                mma_f16(acc[1][2 * np + 1], a[1], bb[2], bb[3]);
            }
        }
        __syncthreads();
    }

    // --- epilogue: z[b][o][tp][sp] ---
#pragma unroll
    for (int mt = 0; mt < 2; ++mt)
#pragma unroll
        for (int rr = 0; rr < 2; ++rr) {
            int o = o0 + wm * 32 + mt * 16 + rr * 8 + g;
            float* zb = g_z + ((size_t)(b * CO + o) * 9 + tp) * 1024;
#pragma unroll
            for (int nt = 0; nt < 8; ++nt) {
                int nl = wn * 64 + nt * 8 + 2 * t4;
                int sp = (pblk * 4 + (nl >> 5)) * 32 + (nl & 31);
                float2 v = make_float2(acc[mt][nt][rr * 2], acc[mt][nt][rr * 2 + 1]);
                *(float2*)(zb + sp) = v;
            }
        }
}

// ---------------------------------------------------------------------------
// Combine: per (b,o) apply separable phase stencil + epilogue.
__global__ void __launch_bounds__(256)
k_comb(const float* __restrict__ noise, const float* __restrict__ nwp,
       const float* __restrict__ ab, float* __restrict__ out) {
    extern __shared__ float sm[];
    float* zs = sm;              // 9 * 1024
    float* us = sm + 9216;       // 3 * 32 * 64

    const int bo = blockIdx.x;
    const int b = bo >> 9, o = bo & 511;
    const int tid = threadIdx.x;

    const float* zp = g_z + (size_t)bo * 9216;
#pragma unroll 4
    for (int j = tid; j < 9216; j += 256) zs[j] = zp[j];
    __syncthreads();

#pragma unroll 1
    for (int j = tid; j < 6144; j += 256) {
        int X = j & 63, y = (j >> 6) & 31, ky = j >> 11;
        int rx = X & 1, q = X >> 1;
        float a = 0.f;
#pragma unroll
        for (int dx = 0; dx < 3; ++dx) {
            int qq = q - 1 + dx;
            if (qq >= 0 && qq < 32) {
#pragma unroll
                for (int kx = 0; kx < 3; ++kx)
                    a += c_M[rx][dx][kx] * zs[(ky * 3 + kx) * 1024 + y * 32 + qq];
            }
        }
        us[j] = a;
    }
    __syncthreads();

    const float alp = g_alpha[b * CO + o];
    const float bia = ab[o];
    const float nw = *nwp;
#pragma unroll 1
    for (int j = tid; j < 4096; j += 256) {
        int X = j & 63, Y = j >> 6;
        int ry = Y & 1, p = Y >> 1;
        float a = 0.f;
#pragma unroll
        for (int dy = 0; dy < 3; ++dy) {
            int pp = p - 1 + dy;
            if (pp >= 0 && pp < 32) {
#pragma unroll
                for (int ky = 0; ky < 3; ++ky)
                    a += c_M[ry][dy][ky] * us[ky * 2048 + pp * 64 + X];
            }
        }
        float v = a * alp + nw * __ldg(&noise[b * 4096 + j]) + bia;
        v = (v > 0.f ? v : 0.2f * v) * 1.4142135623730951f;
        out[(size_t)bo * 4096 + j] = v;
    }
}

// ---------------------------------------------------------------------------
extern "C" void kernel_launch(void* const* d_in, const int* in_sizes, int n_in,
                              void* d_out, int out_size) {
    const float* x           = (const float*)d_in[0];
    const float* style       = (const float*)d_in[1];
    const float* noise       = (const float*)d_in[2];
    const float* conv_weight = (const float*)d_in[3];
    const float* mod_weight  = (const float*)d_in[4];
    const float* mod_bias    = (const float*)d_in[5];
    const float* noise_w     = (const float*)d_in[6];
    const float* act_bias    = (const float*)d_in[7];
    float* out = (float*)d_out;

    cudaFuncSetAttribute(k_zgemm, cudaFuncAttributeMaxDynamicSharedMemorySize, 65536);
    cudaFuncSetAttribute(k_comb, cudaFuncAttributeMaxDynamicSharedMemorySize, 61440);

    k_style<<<NB, 512>>>(style, mod_weight, mod_bias);
    k_w2<<<512, 512>>>(conv_weight);
    k_alpha<<<NB, 512>>>();
    k_xsplit<<<NB * 32, 128>>>(x);
    k_wsplit<<<512, 512>>>(conv_weight);
    k_zgemm<<<dim3(128, 36), 256, 65536>>>();
    k_comb<<<NB * CO, 256, 61440>>>(noise, noise_w, act_bias, out);
}